// round 2
// baseline (speedup 1.0000x reference)
#include <cuda_runtime.h>
#include <math.h>

#define N 2048
#define D 768
#define SCALE 0.036084391824351615f  /* 1/sqrt(768) */

#define NB 48
#define NT 512
#define RPB (D / NB) /* 16 rows per block */

#define SMEM_FLOATS (3*RPB*D + 4*D)
#define SMEM_BYTES (SMEM_FLOATS * 4)

// ---------------- device globals (scratch; no allocations allowed) ----------------
__device__ float g_K1[N*D];
__device__ float g_V1[N*D];
__device__ float g_D1[N*D];   // per-i bias for q1
__device__ float g_Q2[N*D];   // precomputed inter queries
__device__ float g_K2[N*D];
__device__ float g_V2[N*D];
__device__ float g_M [D*D];   // Wq1 @ W_intra[:, :D]
__device__ float g_WD[D*D];   // Wq1 @ W_intra[:, D:]
__device__ float g_WQ[D*D];   // Wq2 @ W_inter
__device__ float g_bD[D];
__device__ float g_bQ[D];
__device__ float g_q1[D];
__device__ float g_e1[N];
__device__ float g_e2[N];
__device__ float g_vacc1[2][D];
__device__ float g_vacc2[2][D];
__device__ float g_sum1[2];
__device__ float g_sum2[2];
__device__ int   g_tmp[N];
__device__ unsigned long long g_bar;

// ---------------- last_same (parallel back-scan) ----------------
__global__ void k_lastsame(const int* __restrict__ spk) {
    int i = blockIdx.x * blockDim.x + threadIdx.x;
    if (i < N) {
        int s = spk[i], r = -1;
        for (int j = i - 1; j >= 0; j--)
            if (spk[j] == s) { r = j; break; }
        g_tmp[i] = r;
    }
}

// ---------------- per-launch state reset (graph replays!) ----------------
__global__ void k_init() {
    int t = threadIdx.x;
    if (t == 0) {
        g_bar = 0ULL;
        g_sum1[0] = g_sum1[1] = 0.f;
        g_sum2[0] = g_sum2[1] = 0.f;
    }
    for (int c = t; c < D; c += blockDim.x) {
        g_vacc1[0][c] = 0.f; g_vacc1[1][c] = 0.f;
        g_vacc2[0][c] = 0.f; g_vacc2[1][c] = 0.f;
    }
}

// ---------------- combined biases: bD = bq1 + Wq1@b_intra ; bQ = bq2 + Wq2@b_inter ----------------
__global__ void k_biascomb(const float* __restrict__ Wq1, const float* __restrict__ bq1,
                           const float* __restrict__ b_intra,
                           const float* __restrict__ Wq2, const float* __restrict__ bq2,
                           const float* __restrict__ b_inter) {
    int r = blockIdx.x * blockDim.x + threadIdx.x;
    if (r < D) {
        float s1 = bq1[r], s2 = bq2[r];
        for (int m = 0; m < D; m++) {
            s1 += Wq1[(size_t)r*D + m] * b_intra[m];
            s2 += Wq2[(size_t)r*D + m] * b_inter[m];
        }
        g_bD[r] = s1; g_bQ[r] = s2;
    }
}

// ---------------- GEMM C[M,Nc] = A[M,K] @ W[Nc,K]^T + bias ----------------
#define GBM 64
#define GBN 64
#define GBK 16
__global__ void __launch_bounds__(256)
k_gemm_nt(const float* __restrict__ A, const float* __restrict__ W,
          const float* __restrict__ bias, float* __restrict__ C,
          int Mr, int Nc, int Kc) {
    __shared__ float As[GBM][GBK + 1];
    __shared__ float Ws[GBN][GBK + 1];
    const int t = threadIdx.x;
    const int tx = t & 15, ty = t >> 4;
    const int m0 = blockIdx.y * GBM, n0 = blockIdx.x * GBN;
    float acc[4][4] = {};
    for (int k0 = 0; k0 < Kc; k0 += GBK) {
        for (int x = t; x < GBM*GBK; x += 256) {
            int m = x >> 4, k = x & 15;
            As[m][k] = A[(size_t)(m0 + m)*Kc + k0 + k];
        }
        for (int x = t; x < GBN*GBK; x += 256) {
            int n = x >> 4, k = x & 15;
            Ws[n][k] = W[(size_t)(n0 + n)*Kc + k0 + k];
        }
        __syncthreads();
        #pragma unroll
        for (int kk = 0; kk < GBK; kk++) {
            float a[4], w[4];
            #pragma unroll
            for (int u = 0; u < 4; u++) a[u] = As[ty*4 + u][kk];
            #pragma unroll
            for (int v = 0; v < 4; v++) w[v] = Ws[tx*4 + v][kk];
            #pragma unroll
            for (int u = 0; u < 4; u++)
                #pragma unroll
                for (int v = 0; v < 4; v++) acc[u][v] += a[u] * w[v];
        }
        __syncthreads();
    }
    #pragma unroll
    for (int u = 0; u < 4; u++)
        #pragma unroll
        for (int v = 0; v < 4; v++) {
            int m = m0 + ty*4 + u, n = n0 + tx*4 + v;
            C[(size_t)m*Nc + n] = acc[u][v] + bias[n];
        }
}

// ---------------- GEMM C[D,D] = A[D,D] @ B[:, boff:boff+D] (row stride ldb) ----------------
__global__ void __launch_bounds__(256)
k_gemm_ab(const float* __restrict__ A, const float* __restrict__ B,
          int ldb, int boff, float* __restrict__ C) {
    __shared__ float As[GBM][GBK + 1];
    __shared__ float Bs[GBK][GBN];
    const int t = threadIdx.x;
    const int tx = t & 15, ty = t >> 4;
    const int m0 = blockIdx.y * GBM, n0 = blockIdx.x * GBN;
    float acc[4][4] = {};
    for (int k0 = 0; k0 < D; k0 += GBK) {
        for (int x = t; x < GBM*GBK; x += 256) {
            int m = x >> 4, k = x & 15;
            As[m][k] = A[(size_t)(m0 + m)*D + k0 + k];
        }
        for (int x = t; x < GBK*GBN; x += 256) {
            int k = x >> 6, n = x & 63;
            Bs[k][n] = B[(size_t)(k0 + k)*ldb + boff + n0 + n];
        }
        __syncthreads();
        #pragma unroll
        for (int kk = 0; kk < GBK; kk++) {
            float a[4], w[4];
            #pragma unroll
            for (int u = 0; u < 4; u++) a[u] = As[ty*4 + u][kk];
            #pragma unroll
            for (int v = 0; v < 4; v++) w[v] = Bs[kk][tx*4 + v];
            #pragma unroll
            for (int u = 0; u < 4; u++)
                #pragma unroll
                for (int v = 0; v < 4; v++) acc[u][v] += a[u] * w[v];
        }
        __syncthreads();
    }
    #pragma unroll
    for (int u = 0; u < 4; u++)
        #pragma unroll
        for (int v = 0; v < 4; v++)
            C[(size_t)(m0 + ty*4 + u)*D + n0 + tx*4 + v] = acc[u][v];
}

// ---------------- grid barrier (monotonic counter + volatile spin) ----------------
__device__ __forceinline__ void grid_bar(unsigned long long& epoch) {
    __syncthreads();
    if (threadIdx.x == 0) {
        __threadfence();
        atomicAdd(&g_bar, 1ULL);
        epoch += (unsigned long long)NB;
        volatile unsigned long long* p = &g_bar;
        while (*p < epoch) { }
        __threadfence();
    }
    __syncthreads();
}

// ---------------- main sequential recurrence (persistent, 48 co-resident CTAs) ----------------
__global__ void __launch_bounds__(NT, 1)
k_main(const float* __restrict__ U,
       const float* __restrict__ Wk2, const float* __restrict__ bk2,
       const float* __restrict__ Wv2, const float* __restrict__ bv2,
       float* __restrict__ Vout) {
    extern __shared__ float sm[];
    float* sM    = sm;                  // RPB*D : rows of M owned by this block
    float* sKw   = sM  + RPB*D;         // RPB*D : rows of Wk2
    float* sVw   = sKw + RPB*D;         // RPB*D : rows of Wv2
    float* sVcur = sVw + RPB*D;         // D
    float* sVprev= sVcur + D;           // D
    float* sQ1   = sVprev + D;          // D
    float* sQ2   = sQ1 + D;             // D

    const int b = blockIdx.x, t = threadIdx.x;
    const int warp = t >> 5, lane = t & 31;
    const int r0 = b * RPB;

    // persistent weight rows into SMEM (one-time)
    for (int x = t; x < RPB*D; x += NT) {
        sM[x]  = g_M[(size_t)r0*D + x];
        sKw[x] = Wk2[(size_t)r0*D + x];
        sVw[x] = Wv2[(size_t)r0*D + x];
    }

    unsigned long long epoch = 0;

    for (int i = 0; i < N; i++) {
        const int tmp = g_tmp[i];
        const int p = i & 1, q = p ^ 1;

        // ============ Phase A : finalize v_{i-1}; q1; K2/V2 row i-1 ============
        if (i > 0) {
            const int tprev = g_tmp[i-1];
            if (tprev < 0) {
                for (int c = t; c < D; c += NT) sVcur[c] = U[(size_t)(i-1)*D + c];
            } else {
                const float inv1 = 1.0f / g_sum1[q];
                const float inv2 = 1.0f / g_sum2[q];
                for (int c = t; c < D; c += NT)
                    sVcur[c] = g_vacc1[q][c]*inv1 + g_vacc2[q][c]*inv2;
            }
        }
        if (tmp >= 0) {
            if (tmp == i-1) {
                for (int c = t; c < D; c += NT) sVprev[c] = sVcur[c];  // same-thread mapping, no race
            } else {
                for (int c = t; c < D; c += NT) sVprev[c] = Vout[(size_t)tmp*D + c];
            }
        }
        __syncthreads();
        if (i > 0 && b == 0) {
            for (int c = t; c < D; c += NT) Vout[(size_t)(i-1)*D + c] = sVcur[c];
        }
        // 48 row-dots (16 q1 + 16 K2 + 16 V2) over 16 warps, weights from SMEM
        for (int rr = warp; rr < 3*RPB; rr += NT/32) {
            const int mat = rr / RPB, r = rr - mat*RPB;
            const float* wrow; const float* vin;
            if (mat == 0) { if (tmp < 0) continue; wrow = sM + r*D; vin = sVprev; }
            else          { if (i == 0)  continue; wrow = (mat == 1 ? sKw : sVw) + r*D; vin = sVcur; }
            float acc = 0.f;
            #pragma unroll 4
            for (int k = lane; k < D; k += 32) acc += wrow[k] * vin[k];
            #pragma unroll
            for (int o = 16; o; o >>= 1) acc += __shfl_xor_sync(0xffffffffu, acc, o);
            if (lane == 0) {
                const int gr = r0 + r;
                if (mat == 0)      g_q1[gr] = acc + g_D1[(size_t)i*D + gr];
                else if (mat == 1) g_K2[(size_t)(i-1)*D + gr] = acc + bk2[gr];
                else               g_V2[(size_t)(i-1)*D + gr] = acc + bv2[gr];
            }
        }
        if (b == 0 && t == 0) { g_sum1[p] = 0.f; g_sum2[p] = 0.f; }
        grid_bar(epoch);

        // ============ Phase B : exp-scores + sums ============
        {   // zero this parity's accumulators (read in next A, written in C below)
            const int gid = b*NT + t;
            if (gid < D) { g_vacc1[p][gid] = 0.f; g_vacc2[p][gid] = 0.f; }
        }
        if (tmp >= 0) {
            for (int c = t; c < D; c += NT) {
                sQ1[c] = g_q1[c];
                sQ2[c] = g_Q2[(size_t)i*D + c];
            }
            __syncthreads();
            const int gw = b*(NT/32) + warp;
            const int GW = NB*(NT/32);
            const float4* q1v = (const float4*)sQ1;
            const float4* q2v = (const float4*)sQ2;
            float lsum1 = 0.f;
            for (int j = gw; j <= i; j += GW) {
                const float4* kr = (const float4*)(g_K1 + (size_t)j*D);
                float acc = 0.f;
                #pragma unroll
                for (int k4 = lane; k4 < D/4; k4 += 32) {
                    float4 kk = kr[k4], qq = q1v[k4];
                    acc += kk.x*qq.x + kk.y*qq.y + kk.z*qq.z + kk.w*qq.w;
                }
                #pragma unroll
                for (int o = 16; o; o >>= 1) acc += __shfl_xor_sync(0xffffffffu, acc, o);
                const float e = expf(acc * SCALE);
                if (lane == 0) { g_e1[j] = e; lsum1 += e; }
            }
            if (lane == 0 && lsum1 != 0.f) atomicAdd(&g_sum1[p], lsum1);
            float lsum2 = 0.f;
            for (int j = tmp + gw; j < i; j += GW) {
                const float4* kr = (const float4*)(g_K2 + (size_t)j*D);
                float acc = 0.f;
                #pragma unroll
                for (int k4 = lane; k4 < D/4; k4 += 32) {
                    float4 kk = kr[k4], qq = q2v[k4];
                    acc += kk.x*qq.x + kk.y*qq.y + kk.z*qq.z + kk.w*qq.w;
                }
                #pragma unroll
                for (int o = 16; o; o >>= 1) acc += __shfl_xor_sync(0xffffffffu, acc, o);
                const float e = expf(acc * SCALE);
                if (lane == 0) { g_e2[j] = e; lsum2 += e; }
            }
            if (lane == 0 && lsum2 != 0.f) atomicAdd(&g_sum2[p], lsum2);
        }
        grid_bar(epoch);

        // ============ Phase C : weighted row-sums into vacc (chunked + atomics) ============
        if (tmp >= 0) {
            {
                const int rows = i + 1;
                const int chunk = (rows + NB - 1) / NB;
                const int jlo = b * chunk;
                const int jhi = min(jlo + chunk, rows);
                if (jlo < jhi) {
                    for (int c = t; c < D; c += NT) {
                        float a = 0.f;
                        for (int j = jlo; j < jhi; j++)
                            a += g_e1[j] * g_V1[(size_t)j*D + c];
                        atomicAdd(&g_vacc1[p][c], a);
                    }
                }
            }
            {
                const int rows = i - tmp;
                const int chunk = (rows + NB - 1) / NB;
                const int jlo = tmp + b * chunk;
                const int jhi = min(jlo + chunk, i);
                if (jlo < jhi) {
                    for (int c = t; c < D; c += NT) {
                        float a = 0.f;
                        for (int j = jlo; j < jhi; j++)
                            a += g_e2[j] * g_V2[(size_t)j*D + c];
                        atomicAdd(&g_vacc2[p][c], a);
                    }
                }
            }
        }
        grid_bar(epoch);
    }

    // ============ epilogue : write V[N-1] ============
    if (b == 0) {
        const int tl = g_tmp[N-1];
        const int pl = (N-1) & 1;
        if (tl < 0) {
            for (int c = t; c < D; c += NT)
                Vout[(size_t)(N-1)*D + c] = U[(size_t)(N-1)*D + c];
        } else {
            const float i1 = 1.0f / g_sum1[pl], i2 = 1.0f / g_sum2[pl];
            for (int c = t; c < D; c += NT)
                Vout[(size_t)(N-1)*D + c] = g_vacc1[pl][c]*i1 + g_vacc2[pl][c]*i2;
        }
    }
}

// ---------------- launch ----------------
extern "C" void kernel_launch(void* const* d_in, const int* in_sizes, int n_in,
                              void* d_out, int out_size) {
    const float* U       = (const float*)d_in[0];
    const int*   spk     = (const int*)  d_in[1];
    const float* W_intra = (const float*)d_in[2];
    const float* b_intra = (const float*)d_in[3];
    const float* W_inter = (const float*)d_in[4];
    const float* b_inter = (const float*)d_in[5];
    const float* Wq1 = (const float*)d_in[6];  const float* bq1 = (const float*)d_in[7];
    const float* Wk1 = (const float*)d_in[8];  const float* bk1 = (const float*)d_in[9];
    const float* Wv1 = (const float*)d_in[10]; const float* bv1 = (const float*)d_in[11];
    const float* Wq2 = (const float*)d_in[12]; const float* bq2 = (const float*)d_in[13];
    const float* Wk2 = (const float*)d_in[14]; const float* bk2 = (const float*)d_in[15];
    const float* Wv2 = (const float*)d_in[16]; const float* bv2 = (const float*)d_in[17];
    float* Vout = (float*)d_out;
    (void)in_sizes; (void)n_in; (void)out_size;

    float *pM, *pWD, *pWQ, *pbD, *pbQ, *pK1, *pV1, *pD1, *pQ2;
    cudaGetSymbolAddress((void**)&pM,  g_M);
    cudaGetSymbolAddress((void**)&pWD, g_WD);
    cudaGetSymbolAddress((void**)&pWQ, g_WQ);
    cudaGetSymbolAddress((void**)&pbD, g_bD);
    cudaGetSymbolAddress((void**)&pbQ, g_bQ);
    cudaGetSymbolAddress((void**)&pK1, g_K1);
    cudaGetSymbolAddress((void**)&pV1, g_V1);
    cudaGetSymbolAddress((void**)&pD1, g_D1);
    cudaGetSymbolAddress((void**)&pQ2, g_Q2);

    cudaFuncSetAttribute(k_main, cudaFuncAttributeMaxDynamicSharedMemorySize, SMEM_BYTES);

    k_lastsame<<<(N + 255)/256, 256>>>(spk);
    k_init<<<1, 256>>>();
    k_biascomb<<<(D + 255)/256, 256>>>(Wq1, bq1, b_intra, Wq2, bq2, b_inter);

    dim3 g12(D/GBN, D/GBM);
    k_gemm_ab<<<g12, 256>>>(Wq1, W_intra, 2*D, 0, pM);   // M  = Wq1 @ W_intra[:, :D]
    k_gemm_ab<<<g12, 256>>>(Wq1, W_intra, 2*D, D, pWD);  // WD = Wq1 @ W_intra[:, D:]
    k_gemm_ab<<<g12, 256>>>(Wq2, W_inter, D,   0, pWQ);  // WQ = Wq2 @ W_inter

    dim3 gNP(D/GBN, N/GBM);
    k_gemm_nt<<<gNP, 256>>>(U, Wk1, bk1, pK1, N, D, D);  // K1
    k_gemm_nt<<<gNP, 256>>>(U, Wv1, bv1, pV1, N, D, D);  // V1
    k_gemm_nt<<<gNP, 256>>>(U, pWD, pbD, pD1, N, D, D);  // D1 (q1 bias per i)
    k_gemm_nt<<<gNP, 256>>>(U, pWQ, pbQ, pQ2, N, D, D);  // Q2 (inter queries)

    k_main<<<NB, NT, SMEM_BYTES>>>(U, Wk2, bk2, Wv2, bv2, Vout);
}

// round 3
// speedup vs baseline: 1.1752x; 1.1752x over previous
#include <cuda_runtime.h>
#include <math.h>

#define N 2048
#define D 768
#define SCALE 0.036084391824351615f  /* 1/sqrt(768) */

#define NB 128
#define NT 512
#define NWARP (NT/32)
#define RPB (D / NB)      /* 6 rows per block */
#define GW (NB * NWARP)   /* 2048 global warps */

/* dynamic smem layout (floats) */
#define OFF_M      0
#define OFF_MW     (RPB*D)
#define OFF_WV2    (2*RPB*D)
#define OFF_VINTRA (3*RPB*D)
#define OFF_PN     (3*RPB*D + D)
#define OFF_VTMP   (3*RPB*D + 2*D)
#define OFF_Q1     (3*RPB*D + 3*D)
#define OFF_Z2     (3*RPB*D + 4*D)
#define OFF_ACC1   (3*RPB*D + 5*D)
#define OFF_ACCP   (3*RPB*D + 6*D)
#define SMEM_FLOATS (3*RPB*D + 7*D)
#define SMEM_BYTES  (SMEM_FLOATS * 4)

// ---------------- device globals ----------------
__device__ float g_K1[N*D];
__device__ float g_V1[N*D];
__device__ float g_D1[N*D];   // scale*(U@WD^T + bD)  (per-i q1 bias)
__device__ float g_Q2[N*D];
__device__ float g_Z2[N*D];   // scale*(Q2@Wk2)
__device__ float g_M [D*D];   // scale*(Wq1 @ W_intra[:, :D])
__device__ float g_MW[D*D];   // g_M @ Wv2
__device__ float g_WD[D*D];   // Wq1 @ W_intra[:, D:]
__device__ float g_WQ[D*D];   // Wq2 @ W_inter
__device__ float g_bD[D];
__device__ float g_bQ[D];
__device__ float g_Mb[D];     // g_M @ bv2
__device__ float g_c2[N];     // scale*(Q2[i]·bk2)
__device__ float g_q1[D];
__device__ float g_vacc1[2][D];
__device__ float g_vaccP[2][D];
__device__ float g_sum1[2];
__device__ float g_sum2[2];
__device__ int   g_tmp[N];
__device__ unsigned long long g_bar;

// ---------------- helpers ----------------
__device__ __forceinline__ float wreduce(float a) {
    #pragma unroll
    for (int o = 16; o; o >>= 1) a += __shfl_xor_sync(0xffffffffu, a, o);
    return a;
}

__device__ __forceinline__ void grid_bar(unsigned long long& epoch) {
    __syncthreads();
    if (threadIdx.x == 0) {
        __threadfence();
        atomicAdd(&g_bar, 1ULL);
        epoch += (unsigned long long)NB;
        volatile unsigned long long* p = &g_bar;
        while (*p < epoch) { }
        __threadfence();
    }
    __syncthreads();
}

// ---------------- last_same ----------------
__global__ void k_lastsame(const int* __restrict__ spk) {
    int i = blockIdx.x * blockDim.x + threadIdx.x;
    if (i < N) {
        int s = spk[i], r = -1;
        for (int j = i - 1; j >= 0; j--)
            if (spk[j] == s) { r = j; break; }
        g_tmp[i] = r;
    }
}

// ---------------- per-launch reset (graph replays) ----------------
__global__ void k_init() {
    int t = threadIdx.x;
    if (t == 0) {
        g_bar = 0ULL;
        g_sum1[0] = g_sum1[1] = 0.f;
        g_sum2[0] = g_sum2[1] = 0.f;
    }
    for (int c = t; c < D; c += blockDim.x) {
        g_vacc1[0][c] = 0.f; g_vacc1[1][c] = 0.f;
        g_vaccP[0][c] = 0.f; g_vaccP[1][c] = 0.f;
    }
}

// ---------------- combined biases ----------------
__global__ void k_biascomb(const float* __restrict__ Wq1, const float* __restrict__ bq1,
                           const float* __restrict__ b_intra,
                           const float* __restrict__ Wq2, const float* __restrict__ bq2,
                           const float* __restrict__ b_inter) {
    int r = blockIdx.x * blockDim.x + threadIdx.x;
    if (r < D) {
        float s1 = bq1[r], s2 = bq2[r];
        for (int m = 0; m < D; m++) {
            s1 += Wq1[(size_t)r*D + m] * b_intra[m];
            s2 += Wq2[(size_t)r*D + m] * b_inter[m];
        }
        g_bD[r] = s1; g_bQ[r] = s2;
    }
}

// ---------------- rowdot: out[i] = alpha * dot(A[i,:D], x) ----------------
__global__ void k_rowdot(const float* __restrict__ A, const float* __restrict__ x,
                         float* __restrict__ out, int M, float alpha) {
    int row = blockIdx.x * 8 + (threadIdx.x >> 5);
    int lane = threadIdx.x & 31;
    if (row < M) {
        float a = 0.f;
        for (int k = lane; k < D; k += 32) a += A[(size_t)row*D + k] * x[k];
        a = wreduce(a);
        if (lane == 0) out[row] = alpha * a;
    }
}

// ---------------- GEMM C = alpha*(A[M,K] @ W[Nc,K]^T + bias) ----------------
#define GBM 64
#define GBN 64
#define GBK 16
__global__ void __launch_bounds__(256)
k_gemm_nt(const float* __restrict__ A, const float* __restrict__ W,
          const float* __restrict__ bias, float* __restrict__ C,
          int Kc, float alpha) {
    __shared__ float As[GBM][GBK + 1];
    __shared__ float Ws[GBN][GBK + 1];
    const int t = threadIdx.x;
    const int tx = t & 15, ty = t >> 4;
    const int m0 = blockIdx.y * GBM, n0 = blockIdx.x * GBN;
    float acc[4][4] = {};
    for (int k0 = 0; k0 < Kc; k0 += GBK) {
        for (int x = t; x < GBM*GBK; x += 256) {
            int m = x >> 4, k = x & 15;
            As[m][k] = A[(size_t)(m0 + m)*Kc + k0 + k];
        }
        for (int x = t; x < GBN*GBK; x += 256) {
            int n = x >> 4, k = x & 15;
            Ws[n][k] = W[(size_t)(n0 + n)*Kc + k0 + k];
        }
        __syncthreads();
        #pragma unroll
        for (int kk = 0; kk < GBK; kk++) {
            float a[4], w[4];
            #pragma unroll
            for (int u = 0; u < 4; u++) a[u] = As[ty*4 + u][kk];
            #pragma unroll
            for (int v = 0; v < 4; v++) w[v] = Ws[tx*4 + v][kk];
            #pragma unroll
            for (int u = 0; u < 4; u++)
                #pragma unroll
                for (int v = 0; v < 4; v++) acc[u][v] += a[u] * w[v];
        }
        __syncthreads();
    }
    #pragma unroll
    for (int u = 0; u < 4; u++)
        #pragma unroll
        for (int v = 0; v < 4; v++) {
            int m = m0 + ty*4 + u, n = n0 + tx*4 + v;
            C[(size_t)m*D + n] = alpha * (acc[u][v] + bias[n]);
        }
}

// ---------------- GEMM C = alpha*(A[:,D] @ B[:, boff:boff+D]) ----------------
__global__ void __launch_bounds__(256)
k_gemm_ab(const float* __restrict__ A, const float* __restrict__ B,
          int ldb, int boff, float* __restrict__ C, float alpha) {
    __shared__ float As[GBM][GBK + 1];
    __shared__ float Bs[GBK][GBN];
    const int t = threadIdx.x;
    const int tx = t & 15, ty = t >> 4;
    const int m0 = blockIdx.y * GBM, n0 = blockIdx.x * GBN;
    float acc[4][4] = {};
    for (int k0 = 0; k0 < D; k0 += GBK) {
        for (int x = t; x < GBM*GBK; x += 256) {
            int m = x >> 4, k = x & 15;
            As[m][k] = A[(size_t)(m0 + m)*D + k0 + k];
        }
        for (int x = t; x < GBK*GBN; x += 256) {
            int k = x >> 6, n = x & 63;
            Bs[k][n] = B[(size_t)(k0 + k)*ldb + boff + n0 + n];
        }
        __syncthreads();
        #pragma unroll
        for (int kk = 0; kk < GBK; kk++) {
            float a[4], w[4];
            #pragma unroll
            for (int u = 0; u < 4; u++) a[u] = As[ty*4 + u][kk];
            #pragma unroll
            for (int v = 0; v < 4; v++) w[v] = Bs[kk][tx*4 + v];
            #pragma unroll
            for (int u = 0; u < 4; u++)
                #pragma unroll
                for (int v = 0; v < 4; v++) acc[u][v] += a[u] * w[v];
        }
        __syncthreads();
    }
    #pragma unroll
    for (int u = 0; u < 4; u++)
        #pragma unroll
        for (int v = 0; v < 4; v++)
            C[(size_t)(m0 + ty*4 + u)*D + n0 + tx*4 + v] = alpha * acc[u][v];
}

// ---------------- main recurrence: 2 grid barriers per step ----------------
__global__ void __launch_bounds__(NT, 1)
k_main(const float* __restrict__ U,
       const float* __restrict__ Wv2, const float* __restrict__ bv2,
       float* __restrict__ Vout) {
    extern __shared__ float sm[];
    float* sM      = sm + OFF_M;
    float* sMW     = sm + OFF_MW;
    float* sWv2    = sm + OFF_WV2;
    float* sVintra = sm + OFF_VINTRA;
    float* sPn     = sm + OFF_PN;
    float* sVtmp   = sm + OFF_VTMP;
    float* sQ1     = sm + OFF_Q1;
    float* sZ2     = sm + OFF_Z2;
    float* sAcc1   = sm + OFF_ACC1;
    float* sAccP   = sm + OFF_ACCP;
    __shared__ float sSum1, sSum2;

    const int b = blockIdx.x, t = threadIdx.x;
    const int warp = t >> 5, lane = t & 31;
    const int gw = b * NWARP + warp;
    const int r0 = b * RPB;

    // persistent weight rows into SMEM (one-time)
    for (int x = t; x < RPB*D; x += NT) {
        sM[x]   = g_M [(size_t)r0*D + x];
        sMW[x]  = g_MW[(size_t)r0*D + x];
        sWv2[x] = Wv2[(size_t)r0*D + x];
    }

    unsigned long long epoch = 0;

    for (int i = 0; i <= N; i++) {
        const int tmp = (i < N) ? g_tmp[i] : -1;

        // ================= Phase A : finalize v_{i-1}; distributed q1 =================
        if (i > 0) {
            const int im1 = i - 1;
            const int tprev = g_tmp[im1];
            const int qa = im1 & 1;
            const bool hv = (tprev >= 0);
            const bool lazy = (tmp == im1);
            const float inv1 = hv ? 1.0f / g_sum1[qa] : 0.f;
            const float inv2 = hv ? 1.0f / g_sum2[qa] : 0.f;
            for (int c = t; c < D; c += NT) {
                sVintra[c] = hv ? g_vacc1[qa][c] * inv1 : U[(size_t)im1*D + c];
                sPn[c]     = hv ? g_vaccP[qa][c] * inv2 : 0.f;
            }
            if (tmp >= 0 && !lazy)
                for (int c = t; c < D; c += NT) sVtmp[c] = Vout[(size_t)tmp*D + c];
            __syncthreads();

            for (int rr = warp; rr < 2*RPB; rr += NWARP) {
                if (rr < RPB) {
                    // v_{i-1}[r0+rr] = v_intra + Wv2[r]·Pn + bv2
                    const float* w = sWv2 + rr*D;
                    float a = 0.f;
                    #pragma unroll 4
                    for (int k = lane; k < D; k += 32) a += w[k] * sPn[k];
                    a = wreduce(a);
                    if (lane == 0) {
                        float v = a + sVintra[r0 + rr];
                        if (hv) v += bv2[r0 + rr];
                        Vout[(size_t)im1*D + r0 + rr] = v;
                    }
                } else if (tmp >= 0) {
                    // q1[r0+r] (scaled): M·v_tmp + D1[i]; lazy path uses M·vintra + MW·Pn (+Mb)
                    const int r = rr - RPB;
                    const float* mrow = sM + r*D;
                    float a = 0.f;
                    if (lazy) {
                        const float* mwrow = sMW + r*D;
                        #pragma unroll 4
                        for (int k = lane; k < D; k += 32)
                            a += mrow[k] * sVintra[k] + mwrow[k] * sPn[k];
                    } else {
                        #pragma unroll 4
                        for (int k = lane; k < D; k += 32) a += mrow[k] * sVtmp[k];
                    }
                    a = wreduce(a);
                    if (lane == 0) {
                        float q = a + g_D1[(size_t)i*D + r0 + r];
                        if (lazy && hv) q += g_Mb[r0 + r];
                        g_q1[r0 + r] = q;
                    }
                }
            }
        }
        grid_bar(epoch);
        if (i == N) break;

        // ================= Phase B : fused scores + accumulation =================
        {
            const int p = i & 1, z = p ^ 1;
            const int gid = b*NT + t;
            if (gid < D) { g_vacc1[z][gid] = 0.f; g_vaccP[z][gid] = 0.f; }
            else if (gid == D) { g_sum1[z] = 0.f; g_sum2[z] = 0.f; }

            if (tmp >= 0) {
                for (int c = t; c < D; c += NT) {
                    sQ1[c] = g_q1[c];
                    sZ2[c] = g_Z2[(size_t)i*D + c];
                    sAcc1[c] = 0.f; sAccP[c] = 0.f;
                }
                if (t == 0) { sSum1 = 0.f; sSum2 = 0.f; }
                __syncthreads();

                const float c2i = g_c2[i];
                const float4* q1v = (const float4*)sQ1;
                const float4* z2v = (const float4*)sZ2;

                // ---- intra rows j = gw (+GW) <= i ----
                for (int j = gw; j <= i; j += GW) {
                    const float4* kr = (const float4*)(g_K1 + (size_t)j*D);
                    const float4* vr = (const float4*)(g_V1 + (size_t)j*D);
                    float4 kk[6], vv[6];
                    #pragma unroll
                    for (int u = 0; u < 6; u++) kk[u] = kr[lane + 32*u];
                    #pragma unroll
                    for (int u = 0; u < 6; u++) vv[u] = vr[lane + 32*u];
                    float acc = 0.f;
                    #pragma unroll
                    for (int u = 0; u < 6; u++) {
                        float4 qq = q1v[lane + 32*u];
                        acc += kk[u].x*qq.x + kk[u].y*qq.y + kk[u].z*qq.z + kk[u].w*qq.w;
                    }
                    acc = wreduce(acc);
                    const float e1 = __expf(acc);
                    #pragma unroll
                    for (int u = 0; u < 6; u++) {
                        int c = 4*(lane + 32*u);
                        atomicAdd(&sAcc1[c+0], e1*vv[u].x);
                        atomicAdd(&sAcc1[c+1], e1*vv[u].y);
                        atomicAdd(&sAcc1[c+2], e1*vv[u].z);
                        atomicAdd(&sAcc1[c+3], e1*vv[u].w);
                    }
                    if (lane == 0) atomicAdd(&sSum1, e1);
                }

                // ---- inter row: j = tmp + (GW-1-gw), if j < i (window < GW always) ----
                {
                    const int j = tmp + (GW - 1 - gw);
                    if (j < i) {
                        const float4* vr = (const float4*)(Vout + (size_t)j*D);
                        float4 vv[6];
                        #pragma unroll
                        for (int u = 0; u < 6; u++) vv[u] = vr[lane + 32*u];
                        float acc = 0.f;
                        #pragma unroll
                        for (int u = 0; u < 6; u++) {
                            float4 zz = z2v[lane + 32*u];
                            acc += vv[u].x*zz.x + vv[u].y*zz.y + vv[u].z*zz.z + vv[u].w*zz.w;
                        }
                        acc = wreduce(acc);
                        const float e2 = __expf(acc + c2i);
                        #pragma unroll
                        for (int u = 0; u < 6; u++) {
                            int c = 4*(lane + 32*u);
                            atomicAdd(&sAccP[c+0], e2*vv[u].x);
                            atomicAdd(&sAccP[c+1], e2*vv[u].y);
                            atomicAdd(&sAccP[c+2], e2*vv[u].z);
                            atomicAdd(&sAccP[c+3], e2*vv[u].w);
                        }
                        if (lane == 0) atomicAdd(&sSum2, e2);
                    }
                }
                __syncthreads();

                // ---- flush block partials to global ----
                if (sSum1 != 0.f || sSum2 != 0.f) {
                    for (int c = t; c < D; c += NT) {
                        atomicAdd(&g_vacc1[p][c], sAcc1[c]);
                        atomicAdd(&g_vaccP[p][c], sAccP[c]);
                    }
                    if (t == 0) {
                        if (sSum1 != 0.f) atomicAdd(&g_sum1[p], sSum1);
                        if (sSum2 != 0.f) atomicAdd(&g_sum2[p], sSum2);
                    }
                }
            }
        }
        grid_bar(epoch);
    }
}

// ---------------- launch ----------------
extern "C" void kernel_launch(void* const* d_in, const int* in_sizes, int n_in,
                              void* d_out, int out_size) {
    const float* U       = (const float*)d_in[0];
    const int*   spk     = (const int*)  d_in[1];
    const float* W_intra = (const float*)d_in[2];
    const float* b_intra = (const float*)d_in[3];
    const float* W_inter = (const float*)d_in[4];
    const float* b_inter = (const float*)d_in[5];
    const float* Wq1 = (const float*)d_in[6];  const float* bq1 = (const float*)d_in[7];
    const float* Wk1 = (const float*)d_in[8];  const float* bk1 = (const float*)d_in[9];
    const float* Wv1 = (const float*)d_in[10]; const float* bv1 = (const float*)d_in[11];
    const float* Wq2 = (const float*)d_in[12]; const float* bq2 = (const float*)d_in[13];
    const float* Wk2 = (const float*)d_in[14]; const float* bk2 = (const float*)d_in[15];
    const float* Wv2 = (const float*)d_in[16]; const float* bv2 = (const float*)d_in[17];
    float* Vout = (float*)d_out;
    (void)in_sizes; (void)n_in; (void)out_size;

    float *pM, *pMW, *pWD, *pWQ, *pbD, *pbQ, *pMb, *pc2;
    float *pK1, *pV1, *pD1, *pQ2, *pZ2;
    cudaGetSymbolAddress((void**)&pM,  g_M);
    cudaGetSymbolAddress((void**)&pMW, g_MW);
    cudaGetSymbolAddress((void**)&pWD, g_WD);
    cudaGetSymbolAddress((void**)&pWQ, g_WQ);
    cudaGetSymbolAddress((void**)&pbD, g_bD);
    cudaGetSymbolAddress((void**)&pbQ, g_bQ);
    cudaGetSymbolAddress((void**)&pMb, g_Mb);
    cudaGetSymbolAddress((void**)&pc2, g_c2);
    cudaGetSymbolAddress((void**)&pK1, g_K1);
    cudaGetSymbolAddress((void**)&pV1, g_V1);
    cudaGetSymbolAddress((void**)&pD1, g_D1);
    cudaGetSymbolAddress((void**)&pQ2, g_Q2);
    cudaGetSymbolAddress((void**)&pZ2, g_Z2);

    cudaFuncSetAttribute(k_main, cudaFuncAttributeMaxDynamicSharedMemorySize, SMEM_BYTES);

    k_lastsame<<<(N + 255)/256, 256>>>(spk);
    k_init<<<1, 256>>>();
    k_biascomb<<<(D + 255)/256, 256>>>(Wq1, bq1, b_intra, Wq2, bq2, b_inter);

    dim3 gDD(D/GBN, D/GBM);
    k_gemm_ab<<<gDD, 256>>>(Wq1, W_intra, 2*D, 0, pM,  SCALE); // M (scaled)
    k_gemm_ab<<<gDD, 256>>>(Wq1, W_intra, 2*D, D, pWD, 1.0f);  // WD
    k_gemm_ab<<<gDD, 256>>>(Wq2, W_inter, D,   0, pWQ, 1.0f);  // WQ
    k_gemm_ab<<<gDD, 256>>>(pM,  Wv2,     D,   0, pMW, 1.0f);  // MW = M@Wv2
    k_rowdot<<<(D + 7)/8, 256>>>(pM, bv2, pMb, D, 1.0f);       // Mb = M@bv2

    dim3 gND(D/GBN, N/GBM);
    k_gemm_nt<<<gND, 256>>>(U, Wk1, bk1, pK1, D, 1.0f);        // K1
    k_gemm_nt<<<gND, 256>>>(U, Wv1, bv1, pV1, D, 1.0f);        // V1
    k_gemm_nt<<<gND, 256>>>(U, pWD, pbD, pD1, D, SCALE);       // D1 (scaled)
    k_gemm_nt<<<gND, 256>>>(U, pWQ, pbQ, pQ2, D, 1.0f);        // Q2
    k_gemm_ab<<<gND, 256>>>(pQ2, Wk2, D, 0, pZ2, SCALE);       // Z2 = scale*Q2@Wk2
    k_rowdot<<<(N + 7)/8, 256>>>(pQ2, bk2, pc2, N, SCALE);     // c2 (scaled)

    k_main<<<NB, NT, SMEM_BYTES>>>(U, Wv2, bv2, Vout);
}